// round 2
// baseline (speedup 1.0000x reference)
#include <cuda_runtime.h>
#include <cstdint>

// Problem: VSC3x3Rulebook
//   inputs: coords[N,3] i32, feats[N,64] f32, in_rows[9,M] i32,
//           out_rows[9,M] i32, weight[9,64,64] f32, bias[64] f32
//   out = scatter_add_{k,m}( feats[in_rows[k,m]] @ weight[k] -> out_rows[k,m] ) + bias
//   d_out (float32): [ float(coords) | out[N,64] ]

#define FULL_MASK 0xffffffffu

__global__ void vsc_coords_cast(const int* __restrict__ coords,
                                float* __restrict__ outc, int n) {
    int idx = blockIdx.x * blockDim.x + threadIdx.x;
    if (idx < n) outc[idx] = (float)coords[idx];
}

__global__ void vsc_init_out(float* __restrict__ out,
                             const float* __restrict__ bias,
                             int total) {
    int idx = blockIdx.x * blockDim.x + threadIdx.x;
    if (idx < total) out[idx] = bias[idx & 63];
}

__global__ __launch_bounds__(256) void vsc_spconv(
    const float* __restrict__ feats,
    const int*   __restrict__ in_rows,
    const int*   __restrict__ out_rows,
    const float* __restrict__ weight,
    float*       __restrict__ out,
    int M, int epb)
{
    __shared__ __align__(16) float Wsm[64 * 64];
    const int k = blockIdx.y;

    // Stage weight[k] (16 KB) into shared memory.
    {
        const float4* src = reinterpret_cast<const float4*>(weight + (size_t)k * 4096);
        float4* dst = reinterpret_cast<float4*>(Wsm);
        #pragma unroll
        for (int i = threadIdx.x; i < 1024; i += 256) dst[i] = src[i];
    }
    __syncthreads();

    const int lane = threadIdx.x & 31;
    const int warp = threadIdx.x >> 5;
    const int half = lane >> 4;   // which entry of the pair this lane serves
    const int lh   = lane & 15;   // lane-in-half: owns output channels [4*lh, 4*lh+4)

    const unsigned wbase = (unsigned)__cvta_generic_to_shared(Wsm);

    const long base      = (long)k * M;
    const int  blk_start = blockIdx.x * epb;
    const int  blk_end   = (blk_start + epb < M) ? (blk_start + epb) : M;

    // 8 warps x 2 entries per iteration = 16 entries / block-iteration
    for (int e0 = blk_start + warp * 2; e0 < blk_end; e0 += 16) {
        const int  eh     = e0 + half;
        const bool valid  = (eh < M);
        const int  ecl    = valid ? eh : (M - 1);
        const int  irow   = __ldg(in_rows  + base + ecl);
        const int  orow   = __ldg(out_rows + base + ecl);

        // Lane (half*16 + g) holds feats[irow][4g .. 4g+3] for its entry.
        const float4 f = *reinterpret_cast<const float4*>(
            feats + (size_t)irow * 64 + (size_t)lh * 4);

        // Packed f32x2 accumulators for channels 4lh..4lh+3
        unsigned long long acc01 = 0ull, acc23 = 0ull;

        #pragma unroll
        for (int g = 0; g < 16; g++) {
            const int src = (half << 4) + g;
            const float f0 = __shfl_sync(FULL_MASK, f.x, src);
            const float f1 = __shfl_sync(FULL_MASK, f.y, src);
            const float f2 = __shfl_sync(FULL_MASK, f.z, src);
            const float f3 = __shfl_sync(FULL_MASK, f.w, src);
            #pragma unroll
            for (int ig = 0; ig < 4; ig++) {
                const float fi = (ig == 0) ? f0 : (ig == 1) ? f1 : (ig == 2) ? f2 : f3;
                const unsigned addr = wbase + ((((4 * g + ig) << 6) + (lh << 2)) << 2);
                unsigned long long w01, w23, fdup;
                asm("ld.shared.v2.u64 {%0, %1}, [%2];"
                    : "=l"(w01), "=l"(w23) : "r"(addr));
                asm("mov.b64 %0, {%1, %1};" : "=l"(fdup) : "f"(fi));
                asm("fma.rn.f32x2 %0, %1, %2, %0;" : "+l"(acc01) : "l"(fdup), "l"(w01));
                asm("fma.rn.f32x2 %0, %1, %2, %0;" : "+l"(acc23) : "l"(fdup), "l"(w23));
            }
        }

        if (valid) {
            float o0, o1, o2, o3;
            asm("mov.b64 {%0, %1}, %2;" : "=f"(o0), "=f"(o1) : "l"(acc01));
            asm("mov.b64 {%0, %1}, %2;" : "=f"(o2), "=f"(o3) : "l"(acc23));
            float4* dst = reinterpret_cast<float4*>(out + (size_t)orow * 64 + (size_t)lh * 4);
            atomicAdd(dst, make_float4(o0, o1, o2, o3));   // unused return -> REDG
        }
    }
}

extern "C" void kernel_launch(void* const* d_in, const int* in_sizes, int n_in,
                              void* d_out, int out_size) {
    const int*   coords   = (const int*)  d_in[0];
    const float* feats    = (const float*)d_in[1];
    const int*   in_rows  = (const int*)  d_in[2];
    const int*   out_rows = (const int*)  d_in[3];
    const float* weight   = (const float*)d_in[4];
    const float* bias     = (const float*)d_in[5];

    const int N = in_sizes[1] / 64;   // feats is [N, 64]
    const int M = in_sizes[2] / 9;    // in_rows is [9, M]

    // d_out is float32: [ float(coords) | out[N,64] ]
    float* outf = (float*)d_out;
    long coords_elems = (long)out_size - (long)N * 64;
    if (coords_elems < 0) coords_elems = 0;
    if (coords_elems > in_sizes[0]) coords_elems = in_sizes[0];

    float* out = outf + coords_elems;

    if (coords_elems > 0) {
        int nc = (int)coords_elems;
        vsc_coords_cast<<<(nc + 255) / 256, 256>>>(coords, outf, nc);
    }

    const int total = N * 64;
    vsc_init_out<<<(total + 255) / 256, 256>>>(out, bias, total);

    const int epb = 256;
    dim3 grid((M + epb - 1) / epb, 9);
    vsc_spconv<<<grid, 256>>>(feats, in_rows, out_rows, weight, out, M, epb);
}

// round 3
// speedup vs baseline: 1.4805x; 1.4805x over previous
#include <cuda_runtime.h>
#include <cstdint>

// VSC3x3Rulebook on GB300.
//   out = scatter_add_{k,m}( feats[in_rows[k,m]] @ weight[k] -> out_rows[k,m] ) + bias
//   d_out (float32): [ float(coords) | out[N,64] ]
//
// Strategy: W register-stationary. Each warp owns a 32-output-channel half;
// lane L keeps the full 64-ci column W[:, co] as 32 packed f32x2 registers
// (even/odd ci pairs). Features are gathered per 64-entry window into smem and
// read back as 16B broadcasts; ci-even/odd partial sums accumulate in f32x2
// lanes, so NO per-FMA packing movs. Epilogue repacks 4 entries through a
// small smem stage into full-warp float4 atomics (REDG.128).

#define CIN   64
#define COUT  64
#define WIN   64            // entries per window per block
#define WINS  16            // windows per block
#define EPB   (WIN * WINS)  // 1024 entries per block
#define FB_STRIDE_F 68      // fbuf row stride in floats (272B, 16B multiple, depads banks)

__device__ float4 Wt_g[9 * 64 * 16];   // [k][co][ci/4] : transposed weights

// ---------- prep: Wt[k][co][ci] = W[k][ci][co] ----------
__global__ void vsc_wprep(const float* __restrict__ weight) {
    const int k = blockIdx.x;            // 9 blocks
    const int t = threadIdx.x;           // 256 threads
    const int co = t & 63;
    for (int c4 = (t >> 6); c4 < 16; c4 += 4) {
        float4 v;
        v.x = weight[(size_t)k * 4096 + (size_t)(4 * c4 + 0) * 64 + co];
        v.y = weight[(size_t)k * 4096 + (size_t)(4 * c4 + 1) * 64 + co];
        v.z = weight[(size_t)k * 4096 + (size_t)(4 * c4 + 2) * 64 + co];
        v.w = weight[(size_t)k * 4096 + (size_t)(4 * c4 + 3) * 64 + co];
        Wt_g[(k * 64 + co) * 16 + c4] = v;
    }
}

__global__ void vsc_coords_cast(const int* __restrict__ coords,
                                float* __restrict__ outc, int n) {
    int idx = blockIdx.x * blockDim.x + threadIdx.x;
    if (idx < n) outc[idx] = (float)coords[idx];
}

__global__ void vsc_init_out(float* __restrict__ out,
                             const float* __restrict__ bias,
                             int total) {
    int idx = blockIdx.x * blockDim.x + threadIdx.x;
    if (idx < total) out[idx] = bias[idx & 63];
}

// ---------- main ----------
__global__ __launch_bounds__(256) void vsc_main(
    const float* __restrict__ feats,
    const int*   __restrict__ in_rows,
    const int*   __restrict__ out_rows,
    float*       __restrict__ out,
    int M)
{
    __shared__ __align__(16) float fbuf[WIN * FB_STRIDE_F]; // gathered features
    __shared__ __align__(16) float stg[8][4][36];           // epilogue stage per warp

    const int k     = blockIdx.y;
    const long kbase = (long)k * M;
    const int tid   = threadIdx.x;
    const int w     = tid >> 5;
    const int lane  = tid & 31;
    const int h     = w & 1;        // co half: 0 -> cos 0..31, 1 -> cos 32..63
    const int pair  = w >> 1;       // 0..3, each pair handles 16 entries/window
    const int co    = h * 32 + lane;

    // ---- load W column for this lane into registers (once per block) ----
    unsigned long long W[32];       // W[2q]={W[4q][co],W[4q+1][co]}, W[2q+1]={W[4q+2],W[4q+3]}
    {
        const float4* wp = &Wt_g[(k * 64 + co) * 16];
        #pragma unroll
        for (int i = 0; i < 16; i++) {
            float4 v = wp[i];
            asm("mov.b64 %0, {%1, %2};" : "=l"(W[2 * i])     : "f"(v.x), "f"(v.y));
            asm("mov.b64 %0, {%1, %2};" : "=l"(W[2 * i + 1]) : "f"(v.z), "f"(v.w));
        }
    }

    const unsigned fb0 = (unsigned)__cvta_generic_to_shared(fbuf);
    const int e_block = blockIdx.x * EPB;

    for (int win = 0; win < WINS; win++) {
        const int e0 = e_block + win * WIN;
        __syncthreads();   // fbuf safe to overwrite

        // ---- gather: 16 lanes per row, 4 passes of 16 entries ----
        #pragma unroll
        for (int g = 0; g < 4; g++) {
            const int el = g * 16 + (tid >> 4);
            const int c  = tid & 15;
            int eg = e0 + el;
            if (eg >= M) eg = M - 1;                       // clamp (tail safety)
            const int irow = __ldg(in_rows + kbase + eg);
            const float4 v = *reinterpret_cast<const float4*>(
                feats + (size_t)irow * 64 + (size_t)c * 4);
            *reinterpret_cast<float4*>(&fbuf[el * FB_STRIDE_F + c * 4]) = v;
        }
        __syncthreads();

        // ---- compute: each warp does its pair's 16 entries, 4 at a time ----
        #pragma unroll 1
        for (int b = 0; b < 4; b++) {
            #pragma unroll
            for (int ee = 0; ee < 4; ee++) {
                const int el = pair * 16 + b * 4 + ee;
                const unsigned fr = fb0 + (unsigned)(el * FB_STRIDE_F * 4);

                unsigned long long a0 = 0ull, a1 = 0ull, a2 = 0ull, a3 = 0ull;
                #pragma unroll
                for (int q = 0; q < 16; q++) {
                    unsigned long long p0, p1;
                    asm("ld.shared.v2.u64 {%0, %1}, [%2];"
                        : "=l"(p0), "=l"(p1) : "r"(fr + (unsigned)(q * 16)));
                    if (q & 1) {
                        asm("fma.rn.f32x2 %0, %1, %2, %0;" : "+l"(a2) : "l"(p0), "l"(W[2 * q]));
                        asm("fma.rn.f32x2 %0, %1, %2, %0;" : "+l"(a3) : "l"(p1), "l"(W[2 * q + 1]));
                    } else {
                        asm("fma.rn.f32x2 %0, %1, %2, %0;" : "+l"(a0) : "l"(p0), "l"(W[2 * q]));
                        asm("fma.rn.f32x2 %0, %1, %2, %0;" : "+l"(a1) : "l"(p1), "l"(W[2 * q + 1]));
                    }
                }
                unsigned long long s01, s23, s;
                asm("add.rn.f32x2 %0, %1, %2;" : "=l"(s01) : "l"(a0), "l"(a1));
                asm("add.rn.f32x2 %0, %1, %2;" : "=l"(s23) : "l"(a2), "l"(a3));
                asm("add.rn.f32x2 %0, %1, %2;" : "=l"(s)   : "l"(s01), "l"(s23));
                float rl, rh;
                asm("mov.b64 {%0, %1}, %2;" : "=f"(rl), "=f"(rh) : "l"(s));
                stg[w][ee][lane] = rl + rh;
            }
            __syncwarp();

            // ---- epilogue: lane j -> (entry j>>3 of batch, quad j&7) ----
            {
                const int eb   = lane >> 3;            // 0..3
                const int q    = lane & 7;             // 0..7 (co quad within half)
                const int el   = pair * 16 + b * 4 + eb;
                const int eg   = e0 + el;
                if (eg < M) {
                    const int orow = __ldg(out_rows + kbase + eg);
                    const float4 vv = *reinterpret_cast<const float4*>(&stg[w][eb][q * 4]);
                    atomicAdd(reinterpret_cast<float4*>(
                        out + (size_t)orow * 64 + h * 32 + q * 4), vv);
                }
            }
            __syncwarp();   // stg reusable next batch
        }
    }
}

extern "C" void kernel_launch(void* const* d_in, const int* in_sizes, int n_in,
                              void* d_out, int out_size) {
    const int*   coords   = (const int*)  d_in[0];
    const float* feats    = (const float*)d_in[1];
    const int*   in_rows  = (const int*)  d_in[2];
    const int*   out_rows = (const int*)  d_in[3];
    const float* weight   = (const float*)d_in[4];
    const float* bias     = (const float*)d_in[5];

    const int N = in_sizes[1] / 64;   // feats is [N, 64]
    const int M = in_sizes[2] / 9;    // in_rows is [9, M]

    // d_out is float32: [ float(coords) | out[N,64] ]
    float* outf = (float*)d_out;
    long coords_elems = (long)out_size - (long)N * 64;
    if (coords_elems < 0) coords_elems = 0;
    if (coords_elems > in_sizes[0]) coords_elems = in_sizes[0];
    float* out = outf + coords_elems;

    if (coords_elems > 0) {
        int nc = (int)coords_elems;
        vsc_coords_cast<<<(nc + 255) / 256, 256>>>(coords, outf, nc);
    }

    vsc_wprep<<<9, 256>>>(weight);

    const int total = N * 64;
    vsc_init_out<<<(total + 255) / 256, 256>>>(out, bias, total);

    dim3 grid((M + EPB - 1) / EPB, 9);
    vsc_main<<<grid, 256>>>(feats, in_rows, out_rows, out, M);
}

// round 5
// speedup vs baseline: 3.1740x; 2.1438x over previous
#include <cuda_runtime.h>
#include <cuda_bf16.h>
#include <cstdint>

// VSC3x3Rulebook on GB300 — mma.sync (HMMA) bf16-split version.
// (tcgen05 is unavailable: harness compiles PTX at compute_103, no 'a' features.)
//   out = scatter_add_{k,m}( feats[in_rows[k,m]] @ weight[k] -> out_rows[k,m] ) + bias
//   d_out (float32): [ float(coords) | out[N,64] ]
//
// Per 128-entry tile: gather feats rows, split f32 -> bf16 hi+lo, store padded
// smem tiles; each warp computes a 32-entry x 32-col slab with
// mma.m16n8k16 (Ahi*Whi + Ahi*Wlo + Alo*Whi, fp32 accum); stage through smem;
// scatter with float4 REDG atomics.

#define TILE_E 128
#define GRID_X 32

// byte offsets inside the static smem block (all rows stride 144B)
#define WLO_OFF 0          // 64 x 144B : bf16 W_lo, [co][ci]
#define AHI_OFF 9216       // 128 x 144B : bf16 A_hi
#define ALO_OFF 27648      // 128 x 144B : bf16 A_lo
#define STG_OFF AHI_OFF    // epilogue stage (8 warps x 2304B) overlaps A_hi
#define SMEM_SZ 46080

__global__ void vsc_coords_cast(const int* __restrict__ coords,
                                float* __restrict__ outc, int n) {
    int i4 = (blockIdx.x * blockDim.x + threadIdx.x) * 4;
    if (i4 + 3 < n) {
        int4 v = *reinterpret_cast<const int4*>(coords + i4);
        *reinterpret_cast<float4*>(outc + i4) =
            make_float4((float)v.x, (float)v.y, (float)v.z, (float)v.w);
    } else {
        for (int j = i4; j < n; j++) outc[j] = (float)coords[j];
    }
}

__global__ void vsc_init_out(float* __restrict__ out,
                             const float* __restrict__ bias,
                             int total) {
    int idx = blockIdx.x * blockDim.x + threadIdx.x;
    if (idx < total) out[idx] = bias[idx & 63];
}

__device__ __forceinline__ uint2 bf16split2(float a, float b) {
    __nv_bfloat16 ha = __float2bfloat16(a);
    __nv_bfloat16 hb = __float2bfloat16(b);
    __nv_bfloat16 la = __float2bfloat16(a - __bfloat162float(ha));
    __nv_bfloat16 lb = __float2bfloat16(b - __bfloat162float(hb));
    uint2 r;
    r.x = (uint32_t)__bfloat16_as_ushort(ha) | ((uint32_t)__bfloat16_as_ushort(hb) << 16);
    r.y = (uint32_t)__bfloat16_as_ushort(la) | ((uint32_t)__bfloat16_as_ushort(lb) << 16);
    return r;
}

__device__ __forceinline__ void mma16816(float* c, const uint32_t* a,
                                         uint32_t b0, uint32_t b1) {
    asm volatile(
        "mma.sync.aligned.m16n8k16.row.col.f32.bf16.bf16.f32 "
        "{%0,%1,%2,%3}, {%4,%5,%6,%7}, {%8,%9}, {%0,%1,%2,%3};"
        : "+f"(c[0]), "+f"(c[1]), "+f"(c[2]), "+f"(c[3])
        : "r"(a[0]), "r"(a[1]), "r"(a[2]), "r"(a[3]), "r"(b0), "r"(b1));
}

#define LDMX4(r, addr)                                                     \
    asm volatile("ldmatrix.sync.aligned.m8n8.x4.shared.b16 "               \
                 "{%0,%1,%2,%3}, [%4];"                                    \
                 : "=r"((r)[0]), "=r"((r)[1]), "=r"((r)[2]), "=r"((r)[3])  \
                 : "r"(addr))
#define LDMX2(r0, r1, addr)                                                \
    asm volatile("ldmatrix.sync.aligned.m8n8.x2.shared.b16 "               \
                 "{%0,%1}, [%2];"                                          \
                 : "=r"(r0), "=r"(r1) : "r"(addr))

__global__ __launch_bounds__(256, 2) void vsc_mma(
    const float* __restrict__ feats,
    const int*   __restrict__ in_rows,
    const int*   __restrict__ out_rows,
    const float* __restrict__ weight,
    float*       __restrict__ out,
    int M, int ntiles)
{
    __shared__ __align__(16) char smem[SMEM_SZ];
    const uint32_t sb = (uint32_t)__cvta_generic_to_shared(smem);

    const int tid   = threadIdx.x;
    const int w     = tid >> 5;
    const int l     = tid & 31;
    const int eslab = w >> 1;    // 0..3 : 32-entry slab
    const int nhalf = w & 1;     // 0/1  : output-column half
    const int k     = blockIdx.y;
    const long kM   = (long)k * M;
    const float* Wg = weight + (size_t)k * 4096;   // [ci][co]

    // ---- W_lo -> smem [co][ci], stride 72 bf16 (144B) ----
    for (int i = tid; i < 4096; i += 256) {
        const int n = i >> 6, ci = i & 63;
        const float v = Wg[(size_t)ci * 64 + n];
        const float lo = v - __bfloat162float(__float2bfloat16(v));
        *reinterpret_cast<__nv_bfloat16*>(smem + WLO_OFF + n * 144 + ci * 2) =
            __float2bfloat16(lo);
    }

    // ---- W_hi fragments -> registers: Bhi[nt][ks][j] ----
    // b_j holds (ci = ks*16 + j*8 + 2*(l&3) +{0,1}, n = nhalf*32 + nt*8 + l/4)
    uint32_t Bhi[4][4][2];
    {
        const int n = nhalf * 32 + (l >> 2);       // l/4 in 0..7 -> +nt*8 below
        #pragma unroll
        for (int nt = 0; nt < 4; nt++)
            #pragma unroll
            for (int ks = 0; ks < 4; ks++)
                #pragma unroll
                for (int j = 0; j < 2; j++) {
                    const int ci0 = ks * 16 + j * 8 + 2 * (l & 3);
                    const float w0 = Wg[(size_t)ci0 * 64 + n + nt * 8];
                    const float w1 = Wg[(size_t)(ci0 + 1) * 64 + n + nt * 8];
                    const __nv_bfloat16 h0 = __float2bfloat16(w0);
                    const __nv_bfloat16 h1 = __float2bfloat16(w1);
                    Bhi[nt][ks][j] = (uint32_t)__bfloat16_as_ushort(h0)
                                   | ((uint32_t)__bfloat16_as_ushort(h1) << 16);
                }
    }
    __syncthreads();

    // ldmatrix lane addresses (constant parts)
    const uint32_t a_row = (l & 7) + ((l >> 3) & 1) * 8;   // + eslab*32 + s*16
    const uint32_t a_kof = (l >> 4) * 8;                   // + ks*16
    const uint32_t b_row = nhalf * 32 + (l & 7);           // + nt*8
    const uint32_t b_kof = ((l >> 3) & 1) * 8;             // + ks*16

    const int er = tid >> 3;   // gather: entry-in-pass 0..31
    const int g8 = tid & 7;    // ci octet

    for (int tile = blockIdx.x; tile < ntiles; tile += GRID_X) {
        const int ebase = tile * TILE_E;

        // ---- gather + split + STS ----
        #pragma unroll
        for (int p = 0; p < 4; p++) {
            const int e = p * 32 + er;
            int eg = ebase + e;
            if (eg >= M) eg = M - 1;
            const int irow = __ldg(in_rows + kM + eg);
            const float4* fp = reinterpret_cast<const float4*>(
                feats + (size_t)irow * 64 + g8 * 8);
            const float4 v0 = __ldg(fp);
            const float4 v1 = __ldg(fp + 1);
            const uint2 p0 = bf16split2(v0.x, v0.y);
            const uint2 p1 = bf16split2(v0.z, v0.w);
            const uint2 p2 = bf16split2(v1.x, v1.y);
            const uint2 p3 = bf16split2(v1.z, v1.w);
            const int off = e * 144 + g8 * 16;
            *reinterpret_cast<uint4*>(smem + AHI_OFF + off) =
                make_uint4(p0.x, p1.x, p2.x, p3.x);
            *reinterpret_cast<uint4*>(smem + ALO_OFF + off) =
                make_uint4(p0.y, p1.y, p2.y, p3.y);
        }
        __syncthreads();

        // ---- compute: 32 entries x 32 cols per warp ----
        float acc[2][4][4];
        #pragma unroll
        for (int s = 0; s < 2; s++)
            #pragma unroll
            for (int nt = 0; nt < 4; nt++)
                #pragma unroll
                for (int r = 0; r < 4; r++) acc[s][nt][r] = 0.f;

        #pragma unroll
        for (int ks = 0; ks < 4; ks++) {
            uint32_t blo[4][2];
            #pragma unroll
            for (int nt = 0; nt < 4; nt++) {
                const uint32_t ba = sb + WLO_OFF
                    + (b_row + nt * 8) * 144 + (ks * 16 + b_kof) * 2;
                LDMX2(blo[nt][0], blo[nt][1], ba);
            }
            #pragma unroll
            for (int s = 0; s < 2; s++) {
                const uint32_t ao =
                    (eslab * 32 + s * 16 + a_row) * 144 + (ks * 16 + a_kof) * 2;
                uint32_t ahi[4], alo[4];
                LDMX4(ahi, sb + AHI_OFF + ao);
                LDMX4(alo, sb + ALO_OFF + ao);
                #pragma unroll
                for (int nt = 0; nt < 4; nt++) {
                    mma16816(acc[s][nt], ahi, Bhi[nt][ks][0], Bhi[nt][ks][1]);
                    mma16816(acc[s][nt], ahi, blo[nt][0],     blo[nt][1]);
                    mma16816(acc[s][nt], alo, Bhi[nt][ks][0], Bhi[nt][ks][1]);
                }
            }
        }
        __syncthreads();   // everyone done reading A; stage area (=A_hi) free

        // ---- epilogue: stage 16 rows at a time, then float4 REDG ----
        float* stg = reinterpret_cast<float*>(smem + STG_OFF + w * 2304); // [16][36]
        #pragma unroll
        for (int s = 0; s < 2; s++) {
            const int r0 = l >> 2;            // 0..7
            const int cb = 2 * (l & 3);       // 0,2,4,6
            #pragma unroll
            for (int nt = 0; nt < 4; nt++) {
                *reinterpret_cast<float2*>(&stg[r0 * 36 + nt * 8 + cb]) =
                    make_float2(acc[s][nt][0], acc[s][nt][1]);
                *reinterpret_cast<float2*>(&stg[(r0 + 8) * 36 + nt * 8 + cb]) =
                    make_float2(acc[s][nt][2], acc[s][nt][3]);
            }
            __syncwarp();
            #pragma unroll
            for (int q = 0; q < 4; q++) {
                const int eloc = q * 4 + (l >> 3);   // 0..15
                const int c    = l & 7;
                const int eg   = ebase + eslab * 32 + s * 16 + eloc;
                if (eg < M) {
                    const int orow = __ldg(out_rows + kM + eg);
                    const float4 v = *reinterpret_cast<const float4*>(
                        &stg[eloc * 36 + c * 4]);
                    atomicAdd(reinterpret_cast<float4*>(
                        out + (size_t)orow * 64 + nhalf * 32 + c * 4), v);
                }
            }
            __syncwarp();
        }
        __syncthreads();   // stage/A reusable next tile
    }
}

extern "C" void kernel_launch(void* const* d_in, const int* in_sizes, int n_in,
                              void* d_out, int out_size) {
    const int*   coords   = (const int*)  d_in[0];
    const float* feats    = (const float*)d_in[1];
    const int*   in_rows  = (const int*)  d_in[2];
    const int*   out_rows = (const int*)  d_in[3];
    const float* weight   = (const float*)d_in[4];
    const float* bias     = (const float*)d_in[5];

    const int N = in_sizes[1] / 64;   // feats is [N, 64]
    const int M = in_sizes[2] / 9;    // in_rows is [9, M]

    // d_out is float32: [ float(coords) | out[N,64] ]
    float* outf = (float*)d_out;
    long coords_elems = (long)out_size - (long)N * 64;
    if (coords_elems < 0) coords_elems = 0;
    if (coords_elems > in_sizes[0]) coords_elems = in_sizes[0];
    float* out = outf + coords_elems;

    if (coords_elems > 0) {
        int nc = (int)coords_elems;
        int nv = (nc + 3) / 4;
        vsc_coords_cast<<<(nv + 255) / 256, 256>>>(coords, outf, nc);
    }

    const int total = N * 64;
    vsc_init_out<<<(total + 255) / 256, 256>>>(out, bias, total);

    const int ntiles = (M + TILE_E - 1) / TILE_E;
    dim3 grid(GRID_X, 9);
    vsc_mma<<<grid, 256>>>(feats, in_rows, out_rows, weight, out, M, ntiles);
}

// round 6
// speedup vs baseline: 4.6666x; 1.4703x over previous
#include <cuda_runtime.h>
#include <cuda_bf16.h>
#include <cstdint>

// VSC3x3Rulebook on GB300 — HMMA bf16-split + TMA bulk-reduce scatter.
//   out = scatter_add_{k,m}( feats[in_rows[k,m]] @ weight[k] -> out_rows[k,m] ) + bias
//   d_out (float32): [ float(coords) | out[N,64] ]
//
// Per 128-entry tile: gather + bf16 hi/lo split -> smem A tiles -> mma.m16n8k16
// (Ahi*Whi + Ahi*Wlo + Alo*Whi, fp32 accum) -> stage 256B rows in smem ->
// one cp.reduce.async.bulk.add.f32 per entry (TMA engine does the RMW).

#define TILE_E 128
#define GRID_X 32

// dynamic smem layout (16B aligned base; all offsets 16B multiples)
#define WLO_OFF 0          // 64 x 144B  : bf16 W_lo, [co][ci]
#define AHI_OFF 9216       // 128 x 144B : bf16 A_hi
#define ALO_OFF 27648      // 128 x 144B : bf16 A_lo
#define STG_OFF 46080      // 128 x 288B : f32 D stage (64 floats + 32B pad)
#define SMEM_SZ 82944

__global__ void vsc_coords_cast(const int* __restrict__ coords,
                                float* __restrict__ outc, int n) {
    int i4 = (blockIdx.x * blockDim.x + threadIdx.x) * 4;
    if (i4 + 3 < n) {
        int4 v = *reinterpret_cast<const int4*>(coords + i4);
        *reinterpret_cast<float4*>(outc + i4) =
            make_float4((float)v.x, (float)v.y, (float)v.z, (float)v.w);
    } else {
        for (int j = i4; j < n; j++) outc[j] = (float)coords[j];
    }
}

__global__ void vsc_init_out(float4* __restrict__ out4,
                             const float4* __restrict__ bias4,
                             int total4) {
    int idx = blockIdx.x * blockDim.x + threadIdx.x;
    if (idx < total4) out4[idx] = bias4[idx & 15];
}

__device__ __forceinline__ uint2 bf16split2(float a, float b) {
    __nv_bfloat16 ha = __float2bfloat16(a);
    __nv_bfloat16 hb = __float2bfloat16(b);
    __nv_bfloat16 la = __float2bfloat16(a - __bfloat162float(ha));
    __nv_bfloat16 lb = __float2bfloat16(b - __bfloat162float(hb));
    uint2 r;
    r.x = (uint32_t)__bfloat16_as_ushort(ha) | ((uint32_t)__bfloat16_as_ushort(hb) << 16);
    r.y = (uint32_t)__bfloat16_as_ushort(la) | ((uint32_t)__bfloat16_as_ushort(lb) << 16);
    return r;
}

__device__ __forceinline__ void mma16816(float* c, const uint32_t* a,
                                         uint32_t b0, uint32_t b1) {
    asm volatile(
        "mma.sync.aligned.m16n8k16.row.col.f32.bf16.bf16.f32 "
        "{%0,%1,%2,%3}, {%4,%5,%6,%7}, {%8,%9}, {%0,%1,%2,%3};"
        : "+f"(c[0]), "+f"(c[1]), "+f"(c[2]), "+f"(c[3])
        : "r"(a[0]), "r"(a[1]), "r"(a[2]), "r"(a[3]), "r"(b0), "r"(b1));
}

#define LDMX4(r, addr)                                                     \
    asm volatile("ldmatrix.sync.aligned.m8n8.x4.shared.b16 "               \
                 "{%0,%1,%2,%3}, [%4];"                                    \
                 : "=r"((r)[0]), "=r"((r)[1]), "=r"((r)[2]), "=r"((r)[3])  \
                 : "r"(addr))
#define LDMX2(r0, r1, addr)                                                \
    asm volatile("ldmatrix.sync.aligned.m8n8.x2.shared.b16 "               \
                 "{%0,%1}, [%2];"                                          \
                 : "=r"(r0), "=r"(r1) : "r"(addr))

__global__ __launch_bounds__(256, 2) void vsc_mma(
    const float* __restrict__ feats,
    const int*   __restrict__ in_rows,
    const int*   __restrict__ out_rows,
    const float* __restrict__ weight,
    float*       __restrict__ out,
    int M, int ntiles)
{
    extern __shared__ __align__(16) char smem[];
    const uint32_t sb = (uint32_t)__cvta_generic_to_shared(smem);

    const int tid   = threadIdx.x;
    const int w     = tid >> 5;
    const int l     = tid & 31;
    const int eslab = w >> 1;    // 0..3 : 32-entry slab
    const int nhalf = w & 1;     // 0/1  : output-column half
    const int k     = blockIdx.y;
    const long kM   = (long)k * M;
    const float* Wg = weight + (size_t)k * 4096;   // [ci][co]

    // ---- W_lo -> smem [co][ci], 144B rows ----
    for (int i = tid; i < 4096; i += 256) {
        const int n = i >> 6, ci = i & 63;
        const float v = Wg[(size_t)ci * 64 + n];
        const float lo = v - __bfloat162float(__float2bfloat16(v));
        *reinterpret_cast<__nv_bfloat16*>(smem + WLO_OFF + n * 144 + ci * 2) =
            __float2bfloat16(lo);
    }

    // ---- W_hi fragments -> registers ----
    uint32_t Bhi[4][4][2];
    {
        const int n = nhalf * 32 + (l >> 2);
        #pragma unroll
        for (int nt = 0; nt < 4; nt++)
            #pragma unroll
            for (int ks = 0; ks < 4; ks++)
                #pragma unroll
                for (int j = 0; j < 2; j++) {
                    const int ci0 = ks * 16 + j * 8 + 2 * (l & 3);
                    const float w0 = Wg[(size_t)ci0 * 64 + n + nt * 8];
                    const float w1 = Wg[(size_t)(ci0 + 1) * 64 + n + nt * 8];
                    Bhi[nt][ks][j] =
                        (uint32_t)__bfloat16_as_ushort(__float2bfloat16(w0))
                      | ((uint32_t)__bfloat16_as_ushort(__float2bfloat16(w1)) << 16);
                }
    }
    __syncthreads();

    const uint32_t a_row = (l & 7) + ((l >> 3) & 1) * 8;
    const uint32_t a_kof = (l >> 4) * 8;
    const uint32_t b_row = nhalf * 32 + (l & 7);
    const uint32_t b_kof = ((l >> 3) & 1) * 8;

    const int er = tid >> 3;
    const int g8 = tid & 7;

    for (int tile = blockIdx.x; tile < ntiles; tile += GRID_X) {
        const int ebase = tile * TILE_E;

        // ---- gather + split + STS (A buffers; stage untouched) ----
        #pragma unroll
        for (int p = 0; p < 4; p++) {
            const int e = p * 32 + er;
            int eg = ebase + e;
            if (eg >= M) eg = M - 1;
            const int irow = __ldg(in_rows + kM + eg);
            const float4* fp = reinterpret_cast<const float4*>(
                feats + (size_t)irow * 64 + g8 * 8);
            const float4 v0 = __ldg(fp);
            const float4 v1 = __ldg(fp + 1);
            const uint2 p0 = bf16split2(v0.x, v0.y);
            const uint2 p1 = bf16split2(v0.z, v0.w);
            const uint2 p2 = bf16split2(v1.x, v1.y);
            const uint2 p3 = bf16split2(v1.z, v1.w);
            const int off = e * 144 + g8 * 16;
            *reinterpret_cast<uint4*>(smem + AHI_OFF + off) =
                make_uint4(p0.x, p1.x, p2.x, p3.x);
            *reinterpret_cast<uint4*>(smem + ALO_OFF + off) =
                make_uint4(p0.y, p1.y, p2.y, p3.y);
        }
        __syncthreads();

        // ---- compute ----
        float acc[2][4][4];
        #pragma unroll
        for (int s = 0; s < 2; s++)
            #pragma unroll
            for (int nt = 0; nt < 4; nt++)
                #pragma unroll
                for (int r = 0; r < 4; r++) acc[s][nt][r] = 0.f;

        #pragma unroll
        for (int ks = 0; ks < 4; ks++) {
            uint32_t blo[4][2];
            #pragma unroll
            for (int nt = 0; nt < 4; nt++) {
                const uint32_t ba = sb + WLO_OFF
                    + (b_row + nt * 8) * 144 + (ks * 16 + b_kof) * 2;
                LDMX2(blo[nt][0], blo[nt][1], ba);
            }
            #pragma unroll
            for (int s = 0; s < 2; s++) {
                const uint32_t ao =
                    (eslab * 32 + s * 16 + a_row) * 144 + (ks * 16 + a_kof) * 2;
                uint32_t ahi[4], alo[4];
                LDMX4(ahi, sb + AHI_OFF + ao);
                LDMX4(alo, sb + ALO_OFF + ao);
                #pragma unroll
                for (int nt = 0; nt < 4; nt++) {
                    mma16816(acc[s][nt], ahi, Bhi[nt][ks][0], Bhi[nt][ks][1]);
                    mma16816(acc[s][nt], ahi, blo[nt][0],     blo[nt][1]);
                    mma16816(acc[s][nt], alo, Bhi[nt][ks][0], Bhi[nt][ks][1]);
                }
            }
        }

        // ---- drain previous tile's bulk reduces, then restage ----
        asm volatile("cp.async.bulk.wait_group 0;" ::: "memory");
        __syncthreads();   // stage free; also all warps past ldmatrix

        {
            const int r0 = l >> 2;            // 0..7
            const int cb = 2 * (l & 3);       // 0,2,4,6
            #pragma unroll
            for (int s = 0; s < 2; s++) {
                const int eb = eslab * 32 + s * 16;
                float* stg = reinterpret_cast<float*>(smem + STG_OFF);
                #pragma unroll
                for (int nt = 0; nt < 4; nt++) {
                    const int c = nhalf * 32 + nt * 8 + cb;
                    *reinterpret_cast<float2*>(&stg[(eb + r0) * 72 + c]) =
                        make_float2(acc[s][nt][0], acc[s][nt][1]);
                    *reinterpret_cast<float2*>(&stg[(eb + r0 + 8) * 72 + c]) =
                        make_float2(acc[s][nt][2], acc[s][nt][3]);
                }
            }
        }
        asm volatile("fence.proxy.async.shared::cta;" ::: "memory");
        __syncthreads();

        // ---- one 256B bulk reduce-add per entry ----
        if (tid < TILE_E) {
            const int eg = ebase + tid;
            if (eg < M) {
                const int orow = __ldg(out_rows + kM + eg);
                const float* dst = out + (size_t)orow * 64;
                const uint32_t src = sb + STG_OFF + tid * 288;
                asm volatile(
                    "cp.reduce.async.bulk.global.shared::cta.bulk_group.add.f32 "
                    "[%0], [%1], 256;"
                    :: "l"(dst), "r"(src) : "memory");
            }
        }
        asm volatile("cp.async.bulk.commit_group;" ::: "memory");
        // no sync: next gather writes A buffers only; stage protected by
        // wait_group + sync at the top of the next epilogue.
    }

    asm volatile("cp.async.bulk.wait_group 0;" ::: "memory");
}

extern "C" void kernel_launch(void* const* d_in, const int* in_sizes, int n_in,
                              void* d_out, int out_size) {
    const int*   coords   = (const int*)  d_in[0];
    const float* feats    = (const float*)d_in[1];
    const int*   in_rows  = (const int*)  d_in[2];
    const int*   out_rows = (const int*)  d_in[3];
    const float* weight   = (const float*)d_in[4];
    const float* bias     = (const float*)d_in[5];

    const int N = in_sizes[1] / 64;   // feats is [N, 64]
    const int M = in_sizes[2] / 9;    // in_rows is [9, M]

    // d_out is float32: [ float(coords) | out[N,64] ]
    float* outf = (float*)d_out;
    long coords_elems = (long)out_size - (long)N * 64;
    if (coords_elems < 0) coords_elems = 0;
    if (coords_elems > in_sizes[0]) coords_elems = in_sizes[0];
    float* out = outf + coords_elems;

    if (coords_elems > 0) {
        int nc = (int)coords_elems;
        int nv = (nc + 3) / 4;
        vsc_coords_cast<<<(nv + 255) / 256, 256>>>(coords, outf, nc);
    }

    const int total4 = N * 16;   // N*64 floats / 4
    vsc_init_out<<<(total4 + 255) / 256, 256>>>(
        (float4*)out, (const float4*)bias, total4);

    cudaFuncSetAttribute(vsc_mma, cudaFuncAttributeMaxDynamicSharedMemorySize,
                         SMEM_SZ);
    const int ntiles = (M + TILE_E - 1) / TILE_E;
    dim3 grid(GRID_X, 9);
    vsc_mma<<<grid, 256, SMEM_SZ>>>(feats, in_rows, out_rows, weight, out,
                                    M, ntiles);
}